// round 5
// baseline (speedup 1.0000x reference)
#include <cuda_runtime.h>

// Problem constants
#define N_ROWS 65536
#define K_CODES 1024
#define D_DIM 256
#define ND (N_ROWS * D_DIM)

// Output layout (reference return order, flattened, fp32):
//   [0, ND)            quantized_out
//   [ND]               quant_loss
//   [ND+1]             util_loss
//   [ND+2]             compact_loss
//   [ND+3, ND+3+N)     vector_indices (as float)

// ---------------- scratch (static device globals; no allocs) ----------------
__device__ float g_sx[N_ROWS];                 // |x_n|^2 (fp32, like reference)
__device__ float g_sw[K_CODES];                // |w_k|^2
__device__ unsigned long long g_best[N_ROWS];  // packed (dist_bits<<32 | code)
__device__ int g_counts[K_CODES];
__device__ double g_sumsq;                     // sum (quantized - x)^2
__device__ double g_pdsum;                     // sum of upper-tri pairwise dists

// ---------------- init (must run every launch: graph replays) ----------------
__global__ void k_init() {
    int t = blockIdx.x * blockDim.x + threadIdx.x;
    if (t < N_ROWS) g_best[t] = 0xFFFFFFFFFFFFFFFFull;
    if (t < K_CODES) g_counts[t] = 0;
    if (t == 0) { g_sumsq = 0.0; g_pdsum = 0.0; }
}

// ---------------- row squared norms: one warp per row ----------------
__global__ void k_rowsq(const float* __restrict__ X, int nrows, int which) {
    int gw = (blockIdx.x * blockDim.x + threadIdx.x) >> 5;
    int lane = threadIdx.x & 31;
    if (gw >= nrows) return;
    const float4* xr = reinterpret_cast<const float4*>(X + (size_t)gw * D_DIM);
    float4 a = xr[lane];
    float4 b = xr[lane + 32];
    float s = a.x * a.x + a.y * a.y + a.z * a.z + a.w * a.w
            + b.x * b.x + b.y * b.y + b.z * b.z + b.w * b.w;
    #pragma unroll
    for (int off = 16; off; off >>= 1) s += __shfl_down_sync(0xffffffffu, s, off);
    if (lane == 0) {
        if (which) g_sw[gw] = s; else g_sx[gw] = s;
    }
}

// ---------------- main: tiled fp32 GEMM (x . w^T) + fused argmin ----------------
#define BM 128
#define BN 128
#define BK 16
#define TM 8
#define TN 8
#define LDA (BM + 8)   // pad: keeps float4 alignment (136*4=544, mult of 16)

__device__ __forceinline__ void ld_tile(const float* __restrict__ base, int k0,
                                        float4 (&r)[2], int tid) {
    #pragma unroll
    for (int i = 0; i < 2; i++) {
        int e = tid + i * 256;
        int row = e >> 2;
        int kq = e & 3;
        r[i] = *reinterpret_cast<const float4*>(base + (size_t)row * D_DIM + k0 + kq * 4);
    }
}

__device__ __forceinline__ void st_tile(float (*S)[LDA], const float4 (&r)[2], int tid) {
    #pragma unroll
    for (int i = 0; i < 2; i++) {
        int e = tid + i * 256;
        int row = e >> 2;
        int kq = e & 3;
        S[kq * 4 + 0][row] = r[i].x;
        S[kq * 4 + 1][row] = r[i].y;
        S[kq * 4 + 2][row] = r[i].z;
        S[kq * 4 + 3][row] = r[i].w;
    }
}

__global__ __launch_bounds__(256, 2)
void k_argmin(const float* __restrict__ X, const float* __restrict__ W) {
    __shared__ __align__(16) float As[2][BK][LDA];
    __shared__ __align__(16) float Bs[2][BK][LDA];

    const int tid = threadIdx.x;
    const int tx = tid & 15;   // code-group
    const int ty = tid >> 4;   // row-group
    const int rowBase = blockIdx.y * BM;
    const int colBase = blockIdx.x * BN;

    const float* Aptr = X + (size_t)rowBase * D_DIM;
    const float* Bptr = W + (size_t)colBase * D_DIM;

    float acc[TM][TN];
    #pragma unroll
    for (int i = 0; i < TM; i++)
        #pragma unroll
        for (int j = 0; j < TN; j++) acc[i][j] = 0.0f;

    float4 ra[2], rb[2];
    // prologue: stage 0
    ld_tile(Aptr, 0, ra, tid);
    ld_tile(Bptr, 0, rb, tid);
    st_tile(As[0], ra, tid);
    st_tile(Bs[0], rb, tid);
    __syncthreads();

    const int NKT = D_DIM / BK;  // 16
    for (int kt = 0; kt < NKT; ++kt) {
        const int cur = kt & 1;
        if (kt + 1 < NKT) {
            ld_tile(Aptr, (kt + 1) * BK, ra, tid);
            ld_tile(Bptr, (kt + 1) * BK, rb, tid);
        }
        #pragma unroll
        for (int k = 0; k < BK; k++) {
            float av[TM], bv[TN];
            *reinterpret_cast<float4*>(&av[0]) = *reinterpret_cast<const float4*>(&As[cur][k][ty * TM]);
            *reinterpret_cast<float4*>(&av[4]) = *reinterpret_cast<const float4*>(&As[cur][k][ty * TM + 4]);
            *reinterpret_cast<float4*>(&bv[0]) = *reinterpret_cast<const float4*>(&Bs[cur][k][tx * TN]);
            *reinterpret_cast<float4*>(&bv[4]) = *reinterpret_cast<const float4*>(&Bs[cur][k][tx * TN + 4]);
            #pragma unroll
            for (int i = 0; i < TM; i++)
                #pragma unroll
                for (int j = 0; j < TN; j++)
                    acc[i][j] = fmaf(av[i], bv[j], acc[i][j]);
        }
        if (kt + 1 < NKT) {
            const int nb = (kt + 1) & 1;
            st_tile(As[nb], ra, tid);
            st_tile(Bs[nb], rb, tid);
        }
        __syncthreads();
    }

    // epilogue: d = fl(fl(sx+sw) - 2*dot), pack (dist,idx), reduce, atomicMin
    float sxr[TM], swc[TN];
    #pragma unroll
    for (int i = 0; i < TM; i++) sxr[i] = g_sx[rowBase + ty * TM + i];
    #pragma unroll
    for (int j = 0; j < TN; j++) swc[j] = g_sw[colBase + tx * TN + j];

    #pragma unroll
    for (int i = 0; i < TM; i++) {
        unsigned long long best = 0xFFFFFFFFFFFFFFFFull;
        #pragma unroll
        for (int j = 0; j < TN; j++) {
            float S = sxr[i] + swc[j];
            float d = S - 2.0f * acc[i][j];     // 2*acc exact; single rounding, matches ref
            unsigned long long key =
                ((unsigned long long)__float_as_uint(d) << 32) |
                (unsigned)(colBase + tx * TN + j);
            if (key < best) best = key;
        }
        #pragma unroll
        for (int off = 8; off; off >>= 1) {
            unsigned long long o = __shfl_down_sync(0xffffffffu, best, off, 16);
            if (o < best) best = o;
        }
        if (tx == 0) atomicMin(&g_best[rowBase + ty * TM + i], best);
    }
}

// ---------------- gather quantized + quant-loss sum + counts + indices ----------------
__global__ void k_gather(const float* __restrict__ X, const float* __restrict__ W,
                         float* __restrict__ out) {
    __shared__ double red[8];
    int gw = (blockIdx.x * blockDim.x + threadIdx.x) >> 5;
    int lane = threadIdx.x & 31;
    int wib = threadIdx.x >> 5;

    double s = 0.0;
    if (gw < N_ROWS) {
        unsigned long long key = g_best[gw];
        int idx = (int)(key & 0xffffffffull);
        if (lane == 0) {
            atomicAdd(&g_counts[idx], 1);
            out[ND + 3 + gw] = (float)idx;
        }
        const float4* wr = reinterpret_cast<const float4*>(W + (size_t)idx * D_DIM);
        const float4* xr = reinterpret_cast<const float4*>(X + (size_t)gw * D_DIM);
        float4* qr = reinterpret_cast<float4*>(out + (size_t)gw * D_DIM);
        #pragma unroll
        for (int i = 0; i < 2; i++) {
            float4 wv = wr[lane + i * 32];
            float4 xv = xr[lane + i * 32];
            qr[lane + i * 32] = wv;  // quantized_out == weight[idx] numerically
            float dx = wv.x - xv.x, dy = wv.y - xv.y, dz = wv.z - xv.z, dw = wv.w - xv.w;
            s += (double)dx * dx + (double)dy * dy + (double)dz * dz + (double)dw * dw;
        }
    }
    #pragma unroll
    for (int off = 16; off; off >>= 1) s += __shfl_down_sync(0xffffffffu, s, off);
    if (lane == 0) red[wib] = s;
    __syncthreads();
    if (threadIdx.x == 0) {
        double t = 0.0;
        #pragma unroll
        for (int i = 0; i < 8; i++) t += red[i];
        atomicAdd(&g_sumsq, t);
    }
}

// ---------------- codebook pairwise distances (compact loss) ----------------
#define CI 8
__global__ void k_compact(const float* __restrict__ W) {
    __shared__ float wi[CI][D_DIM];
    __shared__ float swi[CI];
    __shared__ double red[8];
    int ib = blockIdx.x * CI;

    for (int e = threadIdx.x; e < CI * D_DIM; e += blockDim.x)
        wi[e >> 8][e & 255] = W[(size_t)(ib + (e >> 8)) * D_DIM + (e & 255)];
    if (threadIdx.x < CI) swi[threadIdx.x] = g_sw[ib + threadIdx.x];
    __syncthreads();

    double local = 0.0;
    for (int j = threadIdx.x; j < K_CODES; j += blockDim.x) {
        float dot[CI];
        #pragma unroll
        for (int c = 0; c < CI; c++) dot[c] = 0.0f;
        const float4* wj = reinterpret_cast<const float4*>(W + (size_t)j * D_DIM);
        float swj = g_sw[j];
        for (int k4 = 0; k4 < D_DIM / 4; k4++) {
            float4 v = wj[k4];
            #pragma unroll
            for (int c = 0; c < CI; c++) {
                dot[c] = fmaf(v.x, wi[c][k4 * 4 + 0], dot[c]);
                dot[c] = fmaf(v.y, wi[c][k4 * 4 + 1], dot[c]);
                dot[c] = fmaf(v.z, wi[c][k4 * 4 + 2], dot[c]);
                dot[c] = fmaf(v.w, wi[c][k4 * 4 + 3], dot[c]);
            }
        }
        #pragma unroll
        for (int c = 0; c < CI; c++) {
            if (j > ib + c) {  // upper triangle only, each pair once
                float pd2 = swi[c] + swj - 2.0f * dot[c];
                local += (double)sqrtf(fmaxf(pd2, 1e-12f));
            }
        }
    }
    // warp then block reduce
    #pragma unroll
    for (int off = 16; off; off >>= 1) local += __shfl_down_sync(0xffffffffu, local, off);
    if ((threadIdx.x & 31) == 0) red[threadIdx.x >> 5] = local;
    __syncthreads();
    if (threadIdx.x == 0) {
        double t = 0.0;
        #pragma unroll
        for (int i = 0; i < 8; i++) t += red[i];
        atomicAdd(&g_pdsum, t);
    }
}

// ---------------- scalars ----------------
__global__ void k_final(float* __restrict__ out) {
    __shared__ int ired[256];
    int t = threadIdx.x;
    int c = 0;
    for (int i = t; i < K_CODES; i += 256) {
        int d = g_counts[i] - (N_ROWS / K_CODES);
        c += (d < 0) ? -d : d;
    }
    ired[t] = c;
    __syncthreads();
    for (int off = 128; off; off >>= 1) {
        if (t < off) ired[t] += ired[t + off];
        __syncthreads();
    }
    if (t == 0) {
        out[ND]     = (float)(1.25 * (g_sumsq / (double)ND));           // q + 0.25*e
        out[ND + 1] = (float)((double)ired[0] / (double)K_CODES);       // util
        double npairs = (double)K_CODES * (K_CODES - 1) / 2.0;
        out[ND + 2] = (float)(2.0 * g_pdsum / npairs);                  // compact
    }
}

// ---------------- launch ----------------
extern "C" void kernel_launch(void* const* d_in, const int* in_sizes, int n_in,
                              void* d_out, int out_size) {
    const float* x = (const float*)d_in[0];
    const float* w = (const float*)d_in[1];
    float* out = (float*)d_out;

    k_init<<<(N_ROWS + 255) / 256, 256>>>();
    k_rowsq<<<(N_ROWS * 32) / 256, 256>>>(x, N_ROWS, 0);
    k_rowsq<<<(K_CODES * 32) / 256, 256>>>(w, K_CODES, 1);

    dim3 grid(K_CODES / BN, N_ROWS / BM);  // 8 x 512
    k_argmin<<<grid, 256>>>(x, w);

    k_gather<<<(N_ROWS * 32) / 256, 256>>>(x, w, out);
    k_compact<<<K_CODES / CI, 256>>>(w);
    k_final<<<1, 256>>>(out);
}

// round 8
// speedup vs baseline: 1.1913x; 1.1913x over previous
#include <cuda_runtime.h>
#include <cuda_bf16.h>
#include <cstdint>

#define N_ROWS 65536
#define K_CODES 1024
#define D_DIM 256
#define ND (N_ROWS * D_DIM)

// Output layout (fp32): [0,ND) quantized | [ND] quant_loss | [ND+1] util | [ND+2] compact | [ND+3,+N) indices

// ---------------- scratch (static device globals; no allocs) ----------------
__device__ float g_sx[N_ROWS];
__device__ float g_sw[K_CODES];
__device__ unsigned long long g_best[N_ROWS];
__device__ int g_counts[K_CODES];
__device__ double g_sumsq;
__device__ double g_pdsum;
__device__ int g_nflag;
__device__ int g_flags[N_ROWS];
// Full distance matrix (fp32), written by the tensor GEMM
__device__ float g_dist[(size_t)N_ROWS * K_CODES];                       // 256 MB
// Split scratch: per row 512 bf16 = [hi(256) | lo(256)]
__device__ __align__(16) __nv_bfloat16 g_xsplit[(size_t)N_ROWS * 512];   // 64 MB
__device__ __align__(16) __nv_bfloat16 g_wsplit[(size_t)K_CODES * 512];  // 1 MB

// ---------------- PTX helpers (baseline sm_80+ ISA only) ----------------
#define CP_ASYNC16(dst_u32, src_ptr) \
    asm volatile("cp.async.cg.shared.global [%0], [%1], 16;" :: "r"(dst_u32), "l"(src_ptr) : "memory")
#define CP_COMMIT() asm volatile("cp.async.commit_group;" ::: "memory")
#define CP_WAIT1()  asm volatile("cp.async.wait_group 1;" ::: "memory")
#define CP_WAIT0()  asm volatile("cp.async.wait_group 0;" ::: "memory")

__device__ __forceinline__ void hmma_bf16(float* d, const uint32_t* a, const uint32_t* b) {
    asm volatile(
        "mma.sync.aligned.m16n8k16.row.col.f32.bf16.bf16.f32 "
        "{%0,%1,%2,%3}, {%4,%5,%6,%7}, {%8,%9}, {%0,%1,%2,%3};"
        : "+f"(d[0]), "+f"(d[1]), "+f"(d[2]), "+f"(d[3])
        : "r"(a[0]), "r"(a[1]), "r"(a[2]), "r"(a[3]), "r"(b[0]), "r"(b[1]));
}

// merge two sorted top-2 pairs
__device__ __forceinline__ void top2_merge(unsigned long long& b1, unsigned long long& b2,
                                           unsigned long long o1, unsigned long long o2) {
    if (o1 < b1) {
        unsigned long long nb2 = (b1 < o2) ? b1 : o2;
        b1 = o1; b2 = nb2;
    } else {
        if (o1 < b2) b2 = o1;
    }
}

// ---------------- small kernels ----------------
__global__ void k_init() {
    int t = blockIdx.x * blockDim.x + threadIdx.x;
    if (t < K_CODES) g_counts[t] = 0;
    if (t == 0) { g_sumsq = 0.0; g_pdsum = 0.0; g_nflag = 0; }
}

__global__ void k_rowsq(const float* __restrict__ X, int nrows, int which) {
    int gw = (blockIdx.x * blockDim.x + threadIdx.x) >> 5;
    int lane = threadIdx.x & 31;
    if (gw >= nrows) return;
    const float4* xr = reinterpret_cast<const float4*>(X + (size_t)gw * D_DIM);
    float4 a = xr[lane];
    float4 b = xr[lane + 32];
    float s = a.x * a.x + a.y * a.y + a.z * a.z + a.w * a.w
            + b.x * b.x + b.y * b.y + b.z * b.z + b.w * b.w;
    #pragma unroll
    for (int off = 16; off; off >>= 1) s += __shfl_down_sync(0xffffffffu, s, off);
    if (lane == 0) { if (which) g_sw[gw] = s; else g_sx[gw] = s; }
}

// Split fp32 rows into bf16 hi/lo pairs: dst row = [hi(256) | lo(256)]
__device__ __forceinline__ void split_row_elem(const float* src, __nv_bfloat16* dstbase, int row, int j) {
    float2 v = *reinterpret_cast<const float2*>(src + (size_t)row * D_DIM + 2 * j);
    __nv_bfloat16 h0 = __float2bfloat16(v.x);
    __nv_bfloat16 h1 = __float2bfloat16(v.y);
    __nv_bfloat16 l0 = __float2bfloat16(v.x - __bfloat162float(h0));
    __nv_bfloat16 l1 = __float2bfloat16(v.y - __bfloat162float(h1));
    uint32_t* dst = reinterpret_cast<uint32_t*>(dstbase + (size_t)row * 512);
    dst[j]       = ((uint32_t)__bfloat16_as_ushort(h1) << 16) | (uint32_t)__bfloat16_as_ushort(h0);
    dst[128 + j] = ((uint32_t)__bfloat16_as_ushort(l1) << 16) | (uint32_t)__bfloat16_as_ushort(l0);
}

__global__ void k_xsplit(const float* __restrict__ X) {
    int t = blockIdx.x * blockDim.x + threadIdx.x;
    split_row_elem(X, g_xsplit, t >> 7, t & 127);
}
__global__ void k_wsplitk(const float* __restrict__ W) {
    int t = blockIdx.x * blockDim.x + threadIdx.x;
    split_row_elem(W, g_wsplit, t >> 7, t & 127);
}

// ---------------- main: mma.sync bf16x3 GEMM -> distance matrix ----------------
// CTA: 128 rows x 1024 codes (8 passes of 128). 256 threads = 8 warps (4 row x 2 col).
// Warp tile: 32 rows x 64 codes. K' = 768 in 24 chunks of 32 (hi*hi, hi*lo, lo*hi).
// SMEM chunk: 128 rows x 32 bf16, row stride 80 B (bank = 20g+t4, conflict-free).

#define CHUNK_BYTES 10240              // 128 * 80
#define SM_BUF(buf) ((buf) * 2 * CHUNK_BYTES)

__device__ __forceinline__ int aoff_of(int kc) { return ((kc & 7) + ((kc >= 16) ? 8 : 0)) * 32; }
__device__ __forceinline__ int boff_of(int kc) { return ((kc < 16) ? kc : kc - 16) * 32; }

__global__ __launch_bounds__(256, 2)
void k_mma_dist() {
    __shared__ __align__(16) unsigned char sm[2 * 2 * CHUNK_BYTES];  // 40 KB
    const unsigned char* smp = &sm[0];
    const uint32_t smem_u32 = (uint32_t)__cvta_generic_to_shared(&sm[0]);

    const int tid = threadIdx.x;
    const int wid = tid >> 5, lane = tid & 31;
    const int wr = wid >> 1, wc = wid & 1;
    const int g = lane >> 2, t4 = lane & 3;
    const int rowBase = blockIdx.x * 128;

    const __nv_bfloat16* Arow = g_xsplit + (size_t)rowBase * 512;

    float sx[4];
    #pragma unroll
    for (int i = 0; i < 4; ++i) sx[i] = g_sx[rowBase + wr * 32 + ((i >> 1) * 16) + ((i & 1) * 8) + g];

    for (int cp = 0; cp < 8; ++cp) {
        const __nv_bfloat16* Brow = g_wsplit + (size_t)(cp * 128) * 512;

        float acc[2][8][4];
        #pragma unroll
        for (int mt = 0; mt < 2; ++mt)
            #pragma unroll
            for (int nt = 0; nt < 8; ++nt)
                #pragma unroll
                for (int q = 0; q < 4; ++q) acc[mt][nt][q] = 0.0f;

        // prologue: chunk 0 -> buf 0
        {
            int ao = aoff_of(0), bo = boff_of(0);
            #pragma unroll
            for (int j = 0; j < 2; ++j) {
                int u = tid * 2 + j, r = u >> 2, q = u & 3;
                CP_ASYNC16(smem_u32 + SM_BUF(0) + r * 80 + q * 16, Arow + (size_t)r * 512 + ao + q * 8);
                CP_ASYNC16(smem_u32 + SM_BUF(0) + CHUNK_BYTES + r * 80 + q * 16, Brow + (size_t)r * 512 + bo + q * 8);
            }
            CP_COMMIT();
        }

        for (int kc = 0; kc < 24; ++kc) {
            const int cur = kc & 1;
            if (kc < 23) {
                int ao = aoff_of(kc + 1), bo = boff_of(kc + 1);
                int nb = cur ^ 1;
                #pragma unroll
                for (int j = 0; j < 2; ++j) {
                    int u = tid * 2 + j, r = u >> 2, q = u & 3;
                    CP_ASYNC16(smem_u32 + SM_BUF(nb) + r * 80 + q * 16, Arow + (size_t)r * 512 + ao + q * 8);
                    CP_ASYNC16(smem_u32 + SM_BUF(nb) + CHUNK_BYTES + r * 80 + q * 16, Brow + (size_t)r * 512 + bo + q * 8);
                }
                CP_COMMIT();
                CP_WAIT1();
            } else {
                CP_WAIT0();
            }
            __syncthreads();

            const int A0 = SM_BUF(cur);
            const int B0 = A0 + CHUNK_BYTES;
            #pragma unroll
            for (int ks = 0; ks < 2; ++ks) {
                uint32_t a[2][4];
                #pragma unroll
                for (int mt = 0; mt < 2; ++mt) {
                    int base = A0 + (wr * 32 + mt * 16 + g) * 80 + ks * 32 + t4 * 4;
                    a[mt][0] = *reinterpret_cast<const uint32_t*>(smp + base);
                    a[mt][1] = *reinterpret_cast<const uint32_t*>(smp + base + 8 * 80);
                    a[mt][2] = *reinterpret_cast<const uint32_t*>(smp + base + 16);
                    a[mt][3] = *reinterpret_cast<const uint32_t*>(smp + base + 8 * 80 + 16);
                }
                uint32_t b[8][2];
                #pragma unroll
                for (int nt = 0; nt < 8; ++nt) {
                    int base = B0 + (wc * 64 + nt * 8 + g) * 80 + ks * 32 + t4 * 4;
                    b[nt][0] = *reinterpret_cast<const uint32_t*>(smp + base);
                    b[nt][1] = *reinterpret_cast<const uint32_t*>(smp + base + 16);
                }
                #pragma unroll
                for (int mt = 0; mt < 2; ++mt)
                    #pragma unroll
                    for (int nt = 0; nt < 8; ++nt)
                        hmma_bf16(acc[mt][nt], a[mt], b[nt]);
            }
            __syncthreads();
        }

        // epilogue: d = fl(fl(sx+sw) - 2*dot)  -> store to g_dist
        #pragma unroll
        for (int mt = 0; mt < 2; ++mt) {
            #pragma unroll
            for (int half = 0; half < 2; ++half) {
                const int r = rowBase + wr * 32 + mt * 16 + half * 8 + g;
                const float sxv = sx[mt * 2 + half];
                #pragma unroll
                for (int nt = 0; nt < 8; ++nt) {
                    const int c0 = cp * 128 + wc * 64 + nt * 8 + 2 * t4;
                    float d0 = fmaf(-2.0f, acc[mt][nt][half * 2 + 0], sxv + g_sw[c0]);
                    float d1 = fmaf(-2.0f, acc[mt][nt][half * 2 + 1], sxv + g_sw[c0 + 1]);
                    *reinterpret_cast<float2*>(&g_dist[(size_t)r * K_CODES + c0]) = make_float2(d0, d1);
                }
            }
        }
    }
}

// ---------------- select: per-row top-2, commit or flag ----------------
#define TAU_FLAG 1e-4f

__global__ void k_select() {
    int row = (blockIdx.x * blockDim.x + threadIdx.x) >> 5;
    int lane = threadIdx.x & 31;
    if (row >= N_ROWS) return;

    const float* dr = &g_dist[(size_t)row * K_CODES];
    unsigned long long b1 = 0xFFFFFFFFFFFFFFFFull, b2 = 0xFFFFFFFFFFFFFFFFull;
    #pragma unroll
    for (int s = 0; s < 8; ++s) {
        float4 v = *reinterpret_cast<const float4*>(dr + (s * 32 + lane) * 4);
        int c = (s * 32 + lane) * 4;
        float dv[4] = {v.x, v.y, v.z, v.w};
        #pragma unroll
        for (int q = 0; q < 4; ++q) {
            unsigned long long k = ((unsigned long long)__float_as_uint(dv[q]) << 32) | (unsigned)(c + q);
            if (k < b1) { b2 = b1; b1 = k; }
            else if (k < b2) b2 = k;
        }
    }
    #pragma unroll
    for (int off = 16; off; off >>= 1) {
        unsigned long long o1 = __shfl_down_sync(0xffffffffu, b1, off);
        unsigned long long o2 = __shfl_down_sync(0xffffffffu, b2, off);
        top2_merge(b1, b2, o1, o2);
    }
    if (lane == 0) {
        g_best[row] = b1;
        float d1 = __uint_as_float((uint32_t)(b1 >> 32));
        float d2 = __uint_as_float((uint32_t)(b2 >> 32));
        if (d2 - d1 < TAU_FLAG) {
            int pos = atomicAdd(&g_nflag, 1);
            g_flags[pos] = row;
        }
    }
}

// ---------------- refine flagged rows with R5-exact scalar arithmetic ----------------
__global__ void k_refine(const float* __restrict__ X, const float* __restrict__ W) {
    int gwarp = (blockIdx.x * blockDim.x + threadIdx.x) >> 5;
    int lane = threadIdx.x & 31;
    int nwarps = (gridDim.x * blockDim.x) >> 5;
    int nflag = g_nflag;

    for (int fi = gwarp; fi < nflag; fi += nwarps) {
        int row = g_flags[fi];
        const float* dr = &g_dist[(size_t)row * K_CODES];
        // pass 1: row min of stored d
        float mn = 3.4e38f;
        for (int s = 0; s < 32; ++s) {
            float v = dr[s * 32 + lane];
            if (v < mn) mn = v;
        }
        #pragma unroll
        for (int off = 16; off; off >>= 1) {
            float o = __shfl_xor_sync(0xffffffffu, mn, off);
            if (o < mn) mn = o;
        }
        // pass 2: refine candidates with sequential fp32 dot (R5 arithmetic)
        const float thresh = mn + 2e-4f;
        const float sx = g_sx[row];
        const float* xrow = X + (size_t)row * D_DIM;
        unsigned long long best = 0xFFFFFFFFFFFFFFFFull;
        for (int s = 0; s < 32; ++s) {
            int c = s * 32 + lane;
            if (dr[c] <= thresh) {
                const float* wrow = W + (size_t)c * D_DIM;
                float acc = 0.0f;
                for (int k = 0; k < D_DIM; ++k) acc = fmaf(xrow[k], wrow[k], acc);
                float d = fmaf(-2.0f, acc, sx + g_sw[c]);
                unsigned long long key = ((unsigned long long)__float_as_uint(d) << 32) | (unsigned)c;
                if (key < best) best = key;
            }
        }
        #pragma unroll
        for (int off = 16; off; off >>= 1) {
            unsigned long long o = __shfl_xor_sync(0xffffffffu, best, off);
            if (o < best) best = o;
        }
        if (lane == 0) g_best[row] = best;
    }
}

// ---------------- gather quantized + quant-loss sum + counts + indices ----------------
__global__ void k_gather(const float* __restrict__ X, const float* __restrict__ W,
                         float* __restrict__ out) {
    __shared__ double red[8];
    int gw = (blockIdx.x * blockDim.x + threadIdx.x) >> 5;
    int lane = threadIdx.x & 31;
    int wib = threadIdx.x >> 5;

    double s = 0.0;
    if (gw < N_ROWS) {
        unsigned long long key = g_best[gw];
        int idx = (int)(key & 0xffffffffull);
        if (lane == 0) {
            atomicAdd(&g_counts[idx], 1);
            out[ND + 3 + gw] = (float)idx;
        }
        const float4* wr4 = reinterpret_cast<const float4*>(W + (size_t)idx * D_DIM);
        const float4* xr = reinterpret_cast<const float4*>(X + (size_t)gw * D_DIM);
        float4* qr = reinterpret_cast<float4*>(out + (size_t)gw * D_DIM);
        #pragma unroll
        for (int i = 0; i < 2; i++) {
            float4 wv = wr4[lane + i * 32];
            float4 xv = xr[lane + i * 32];
            qr[lane + i * 32] = wv;
            float dx = wv.x - xv.x, dy = wv.y - xv.y, dz = wv.z - xv.z, dw = wv.w - xv.w;
            s += (double)dx * dx + (double)dy * dy + (double)dz * dz + (double)dw * dw;
        }
    }
    #pragma unroll
    for (int off = 16; off; off >>= 1) s += __shfl_down_sync(0xffffffffu, s, off);
    if (lane == 0) red[wib] = s;
    __syncthreads();
    if (threadIdx.x == 0) {
        double tt = 0.0;
        #pragma unroll
        for (int i = 0; i < 8; i++) tt += red[i];
        atomicAdd(&g_sumsq, tt);
    }
}

// ---------------- codebook pairwise distances (compact loss) ----------------
#define CI 8
__global__ void k_compact(const float* __restrict__ W) {
    __shared__ float wi[CI][D_DIM];
    __shared__ float swi[CI];
    __shared__ double red[8];
    int ib = blockIdx.x * CI;

    for (int e = threadIdx.x; e < CI * D_DIM; e += blockDim.x)
        wi[e >> 8][e & 255] = W[(size_t)(ib + (e >> 8)) * D_DIM + (e & 255)];
    if (threadIdx.x < CI) swi[threadIdx.x] = g_sw[ib + threadIdx.x];
    __syncthreads();

    double local = 0.0;
    for (int j = threadIdx.x; j < K_CODES; j += blockDim.x) {
        float dot[CI];
        #pragma unroll
        for (int c = 0; c < CI; c++) dot[c] = 0.0f;
        const float4* wj = reinterpret_cast<const float4*>(W + (size_t)j * D_DIM);
        float swj = g_sw[j];
        for (int k4 = 0; k4 < D_DIM / 4; k4++) {
            float4 v = wj[k4];
            #pragma unroll
            for (int c = 0; c < CI; c++) {
                dot[c] = fmaf(v.x, wi[c][k4 * 4 + 0], dot[c]);
                dot[c] = fmaf(v.y, wi[c][k4 * 4 + 1], dot[c]);
                dot[c] = fmaf(v.z, wi[c][k4 * 4 + 2], dot[c]);
                dot[c] = fmaf(v.w, wi[c][k4 * 4 + 3], dot[c]);
            }
        }
        #pragma unroll
        for (int c = 0; c < CI; c++) {
            if (j > ib + c) {
                float pd2 = swi[c] + swj - 2.0f * dot[c];
                local += (double)sqrtf(fmaxf(pd2, 1e-12f));
            }
        }
    }
    #pragma unroll
    for (int off = 16; off; off >>= 1) local += __shfl_down_sync(0xffffffffu, local, off);
    if ((threadIdx.x & 31) == 0) red[threadIdx.x >> 5] = local;
    __syncthreads();
    if (threadIdx.x == 0) {
        double tt = 0.0;
        #pragma unroll
        for (int i = 0; i < 8; i++) tt += red[i];
        atomicAdd(&g_pdsum, tt);
    }
}

// ---------------- scalars ----------------
__global__ void k_final(float* __restrict__ out) {
    __shared__ int ired[256];
    int t = threadIdx.x;
    int c = 0;
    for (int i = t; i < K_CODES; i += 256) {
        int d = g_counts[i] - (N_ROWS / K_CODES);
        c += (d < 0) ? -d : d;
    }
    ired[t] = c;
    __syncthreads();
    for (int off = 128; off; off >>= 1) {
        if (t < off) ired[t] += ired[t + off];
        __syncthreads();
    }
    if (t == 0) {
        out[ND]     = (float)(1.25 * (g_sumsq / (double)ND));
        out[ND + 1] = (float)((double)ired[0] / (double)K_CODES);
        double npairs = (double)K_CODES * (K_CODES - 1) / 2.0;
        out[ND + 2] = (float)(2.0 * g_pdsum / npairs);
    }
}

// ---------------- launch ----------------
extern "C" void kernel_launch(void* const* d_in, const int* in_sizes, int n_in,
                              void* d_out, int out_size) {
    const float* x = (const float*)d_in[0];
    const float* w = (const float*)d_in[1];
    float* out = (float*)d_out;

    k_init<<<(K_CODES + 255) / 256, 256>>>();
    k_rowsq<<<(N_ROWS * 32) / 256, 256>>>(x, N_ROWS, 0);
    k_rowsq<<<(K_CODES * 32) / 256, 256>>>(w, K_CODES, 1);
    k_xsplit<<<(N_ROWS * 128) / 256, 256>>>(x);
    k_wsplitk<<<(K_CODES * 128) / 256, 256>>>(w);

    k_mma_dist<<<N_ROWS / 128, 256>>>();

    k_select<<<(N_ROWS * 32) / 256, 256>>>();
    k_refine<<<296, 256>>>(x, w);

    k_gather<<<(N_ROWS * 32) / 256, 256>>>(x, w, out);
    k_compact<<<K_CODES / CI, 256>>>(w);
    k_final<<<1, 256>>>(out);
}